// round 17
// baseline (speedup 1.0000x reference)
#include <cuda_runtime.h>
#include <cuda_fp16.h>
#include <cstdint>

#define N_NODES 50000
#define EMAX    1000000
#define CH      128

// Scratch (device globals -- no allocation allowed)
__device__ __align__(16) __half g_xh[(size_t)N_NODES * CH];   // x fp16
__device__ __align__(16) __half g_h1h[(size_t)N_NODES * CH];  // h1 fp16
__device__ __align__(16) __half g_aggh[(size_t)N_NODES * CH]; // mean-agg fp16
__device__ int g_cnt[N_NODES];
__device__ int g_row[N_NODES + 1];
__device__ int g_cursor[N_NODES];
__device__ int g_col[EMAX];
__device__ int g_is64;

// pre-transposed fp16 weights: Wt[n][k], k contiguous
__device__ __align__(16) __half g_W1t[128 * 256];
__device__ __align__(16) __half g_W2t[128 * 256];
__device__ __align__(16) __half g_Wdt[128 * 128];

__device__ __forceinline__ uint32_t h2pack(float x, float y) {
    __half2 h = __floats2half2_rn(x, y);
    return *(uint32_t*)&h;
}

__device__ __forceinline__ int edge_at(const void* e, int i) {
    return g_is64 ? (int)((const long long*)e)[i] : ((const int*)e)[i];
}

// ---------------------------------------------------------------------------
// prep: ONE kernel -- convert x->fp16, clear g_cnt, transpose+convert weights,
// and (block 0) detect edge dtype. grid = (n*CH/8 + 255)/256 = 3125.
// ---------------------------------------------------------------------------
__global__ void prep_kernel(const unsigned* __restrict__ e,
                            const float* __restrict__ x,
                            const float* __restrict__ W1l,
                            const float* __restrict__ W1r,
                            const float* __restrict__ W2l,
                            const float* __restrict__ W2r,
                            const float* __restrict__ Wd,
                            int n) {
    int b = blockIdx.x;
    int t = threadIdx.x;
    int gid = b * 256 + t;

    // x -> fp16 (8 floats/thread)
    int total = n * CH / 8;
    if (gid < total) {
        const float4* p = (const float4*)x + (size_t)gid * 2;
        float4 v0 = p[0], v1 = p[1];
        uint4 o;
        o.x = h2pack(v0.x, v0.y);  o.y = h2pack(v0.z, v0.w);
        o.z = h2pack(v1.x, v1.y);  o.w = h2pack(v1.z, v1.w);
        *((uint4*)g_xh + gid) = o;
    }
    // clear degree counters
    if (gid < n) g_cnt[gid] = 0;
    // weights: transpose + fp16 (81920 elements)
    if (gid < 32768) {
        int nn = gid >> 8, k = gid & 255;
        float v = (k < 128) ? W1l[(size_t)k * CH + nn]
                            : W1r[(size_t)(k - 128) * CH + nn];
        g_W1t[nn * 256 + k] = __float2half(v);
    } else if (gid < 65536) {
        int r = gid - 32768;
        int nn = r >> 8, k = r & 255;
        float v = (k < 128) ? W2l[(size_t)k * CH + nn]
                            : W2r[(size_t)(k - 128) * CH + nn];
        g_W2t[nn * 256 + k] = __float2half(v);
    } else if (gid < 81920) {
        int r = gid - 65536;
        int nn = r >> 7, k = r & 127;
        g_Wdt[nn * 128 + k] = __float2half(Wd[(size_t)k * CH + nn]);
    }
    // detect: int64 edges have zero odd words (values < 2^31)
    if (b == 0) {
        __shared__ unsigned red[256];
        unsigned acc = 0;
        #pragma unroll
        for (int j = 0; j < 8; j++) acc |= e[(t * 8 + j) * 2 + 1];
        red[t] = acc;
        __syncthreads();
        for (int s = 128; s > 0; s >>= 1) {
            if (t < s) red[t] |= red[t + s];
            __syncthreads();
        }
        if (t == 0) g_is64 = (red[0] == 0) ? 1 : 0;
    }
}

// ---------------------------------------------------------------------------
// hist: degree histogram, 4 edges/thread (int4 loads on int32 path)
// ---------------------------------------------------------------------------
__global__ void hist_kernel(const void* __restrict__ edge, int E, int n) {
    int base = (blockIdx.x * blockDim.x + threadIdx.x) * 4;
    if (base >= E) return;
    if (!g_is64 && base + 3 < E) {
        int4 d4 = *((const int4*)((const int*)edge + E) + base / 4);
        if ((unsigned)d4.x < (unsigned)n) atomicAdd(&g_cnt[d4.x], 1);
        if ((unsigned)d4.y < (unsigned)n) atomicAdd(&g_cnt[d4.y], 1);
        if ((unsigned)d4.z < (unsigned)n) atomicAdd(&g_cnt[d4.z], 1);
        if ((unsigned)d4.w < (unsigned)n) atomicAdd(&g_cnt[d4.w], 1);
    } else {
        #pragma unroll
        for (int j = 0; j < 4; j++) {
            int k = base + j;
            if (k < E) {
                int d = edge_at(edge, E + k);
                if ((unsigned)d < (unsigned)n) atomicAdd(&g_cnt[d], 1);
            }
        }
    }
}

// ---------------------------------------------------------------------------
// scan: single-block exclusive scan of g_cnt -> g_row, zero g_cursor.
// 1024 threads, warp-shuffle block scan, tiles of 1024.
// ---------------------------------------------------------------------------
__global__ void scan_kernel(int n, int E) {
    __shared__ int wsum[32];
    __shared__ int s_carry;
    int t = threadIdx.x;
    int lane = t & 31;
    int wid = t >> 5;
    if (t == 0) s_carry = 0;
    __syncthreads();

    int ntiles = (n + 1023) >> 10;
    for (int tile = 0; tile < ntiles; tile++) {
        int idx = (tile << 10) + t;
        int v = (idx < n) ? g_cnt[idx] : 0;
        // warp inclusive scan
        int x = v;
        #pragma unroll
        for (int o = 1; o < 32; o <<= 1) {
            int y = __shfl_up_sync(0xFFFFFFFFu, x, o);
            if (lane >= o) x += y;
        }
        if (lane == 31) wsum[wid] = x;
        __syncthreads();
        if (wid == 0) {
            int s = wsum[lane];
            #pragma unroll
            for (int o = 1; o < 32; o <<= 1) {
                int y = __shfl_up_sync(0xFFFFFFFFu, s, o);
                if (lane >= o) s += y;
            }
            wsum[lane] = s;
        }
        __syncthreads();
        int carry = s_carry;
        int excl = carry + (wid ? wsum[wid - 1] : 0) + (x - v);
        if (idx < n) {
            g_row[idx] = excl;
            g_cursor[idx] = 0;
        }
        __syncthreads();                 // everyone read s_carry/wsum
        if (t == 0) s_carry = carry + wsum[31];
        __syncthreads();
    }
    if (t == 0) g_row[n] = E;
}

// ---------------------------------------------------------------------------
// fill: CSR column fill, 4 edges/thread
// ---------------------------------------------------------------------------
__device__ __forceinline__ void fill_one(int s, int d, int n) {
    if ((unsigned)d >= (unsigned)n) return;
    if ((unsigned)s >= (unsigned)n) s = 0;
    int pos = g_row[d] + atomicAdd(&g_cursor[d], 1);
    g_col[pos] = s;
}

__global__ void fill_kernel(const void* __restrict__ edge, int E, int n) {
    int base = (blockIdx.x * blockDim.x + threadIdx.x) * 4;
    if (base >= E) return;
    if (!g_is64 && base + 3 < E) {
        int4 s4 = *((const int4*)((const int*)edge) + base / 4);
        int4 d4 = *((const int4*)((const int*)edge + E) + base / 4);
        fill_one(s4.x, d4.x, n);
        fill_one(s4.y, d4.y, n);
        fill_one(s4.z, d4.z, n);
        fill_one(s4.w, d4.w, n);
    } else {
        #pragma unroll
        for (int j = 0; j < 4; j++) {
            int k = base + j;
            if (k < E)
                fill_one(edge_at(edge, k), edge_at(edge, E + k), n);
        }
    }
}

// ---------------------------------------------------------------------------
// aggregate: one warp per destination row, fp16 gather, fp32 accumulate,
// mean folded in, fp16 output. SRC 0: g_xh. SRC 1: g_h1h. -> g_aggh.
// ---------------------------------------------------------------------------
template <int SRC>
__global__ void aggregate_kernel(int n) {
    int row = (blockIdx.x * blockDim.x + threadIdx.x) >> 5;
    int lane = threadIdx.x & 31;
    if (row >= n) return;

    const __half* __restrict__ feat = (SRC == 0) ? g_xh : g_h1h;

    int base = g_row[row];
    int end  = g_row[row + 1];
    int deg  = end - base;

    float a0 = 0.f, a1 = 0.f, a2 = 0.f, a3 = 0.f;
    int j = base;
    for (; j + 3 < end; j += 4) {
        int s0 = g_col[j],     s1 = g_col[j + 1];
        int s2 = g_col[j + 2], s3 = g_col[j + 3];
        uint2 u0 = *(const uint2*)(feat + (size_t)s0 * CH + lane * 4);
        uint2 u1 = *(const uint2*)(feat + (size_t)s1 * CH + lane * 4);
        uint2 u2 = *(const uint2*)(feat + (size_t)s2 * CH + lane * 4);
        uint2 u3 = *(const uint2*)(feat + (size_t)s3 * CH + lane * 4);
        float2 f0a = __half22float2(*(__half2*)&u0.x), f0b = __half22float2(*(__half2*)&u0.y);
        float2 f1a = __half22float2(*(__half2*)&u1.x), f1b = __half22float2(*(__half2*)&u1.y);
        float2 f2a = __half22float2(*(__half2*)&u2.x), f2b = __half22float2(*(__half2*)&u2.y);
        float2 f3a = __half22float2(*(__half2*)&u3.x), f3b = __half22float2(*(__half2*)&u3.y);
        a0 += (f0a.x + f1a.x) + (f2a.x + f3a.x);
        a1 += (f0a.y + f1a.y) + (f2a.y + f3a.y);
        a2 += (f0b.x + f1b.x) + (f2b.x + f3b.x);
        a3 += (f0b.y + f1b.y) + (f2b.y + f3b.y);
    }
    for (; j < end; j++) {
        int s0 = g_col[j];
        uint2 u0 = *(const uint2*)(feat + (size_t)s0 * CH + lane * 4);
        float2 fa = __half22float2(*(__half2*)&u0.x), fb = __half22float2(*(__half2*)&u0.y);
        a0 += fa.x; a1 += fa.y; a2 += fb.x; a3 += fb.y;
    }

    float sc = 1.0f / fmaxf((float)deg, 1.0f);
    uint2 o;
    o.x = h2pack(a0 * sc, a1 * sc);
    o.y = h2pack(a2 * sc, a3 * sc);
    *(uint2*)(g_aggh + (size_t)row * CH + lane * 4) = o;
}

// ---------------------------------------------------------------------------
// GEMM via mma.sync m16n8k16 fp16 (HMMA), single pass, fp16 operands
// everywhere (pre-converted). BM=64, BN=128, KC=32. 8 warps 2(M) x 4(N).
// MODE 1: relu( [agg | x ] @ W1t + b1 ) -> g_h1h                  (K=256)
// MODE 2 (FUSED): h2 = relu( [agg | h1] @ W2t + b2 ) kept in smem,
//                 then out = alpha*(h2 @ Wdt + bd) + (1-alpha)*x   (K=128)
// ---------------------------------------------------------------------------
#define BM 64
#define KC 32
#define ASTR 40
#define H2STR 136

__device__ __forceinline__ void mma_f16(float* d, const uint32_t* a,
                                        const uint32_t* b) {
    asm volatile(
        "mma.sync.aligned.m16n8k16.row.col.f32.f16.f16.f32 "
        "{%0,%1,%2,%3}, {%4,%5,%6,%7}, {%8,%9}, {%0,%1,%2,%3};"
        : "+f"(d[0]), "+f"(d[1]), "+f"(d[2]), "+f"(d[3])
        : "r"(a[0]), "r"(a[1]), "r"(a[2]), "r"(a[3]), "r"(b[0]), "r"(b[1]));
}

template <int MODE>
__global__ __launch_bounds__(256) void gemm_kernel(
    const float* __restrict__ bias,    // b1 or b2
    const float* __restrict__ bd,      // MODE 2
    const float* __restrict__ xres,    // MODE 2
    const float* __restrict__ alpha_p, // MODE 2
    float* __restrict__ out_ext,       // MODE 2
    int n)
{
    __shared__ __half As[BM][ASTR];
    __shared__ __half Bs[128][ASTR];
    __shared__ __half H2[BM][H2STR];   // MODE 2 only
    __shared__ float s_bias[128];
    __shared__ float s_bd[128];

    int t = threadIdx.x;
    int lane = t & 31;
    int w = t >> 5;
    int wm = w >> 2;
    int wn = w & 3;
    int block_row = blockIdx.x * BM;

    if (t < 128) {
        s_bias[t] = bias[t];
        if (MODE == 2) s_bd[t] = bd[t];
    }

    float acc[2][4][4];
    #pragma unroll
    for (int mi = 0; mi < 2; mi++)
        #pragma unroll
        for (int nj = 0; nj < 4; nj++)
            #pragma unroll
            for (int q = 0; q < 4; q++) acc[mi][nj][q] = 0.f;

    const __half* Wt = (MODE == 1) ? g_W1t : g_W2t;

    int bnn = t >> 1;
    int bks = (t & 1) * 16;

    // ================= GEMM 1: [agg | self] @ Wt =================
    #pragma unroll 1
    for (int c = 0; c < 8; c++) {
        const __half* Asrc = (c < 4) ? g_aggh : ((MODE == 1) ? g_xh : g_h1h);
        int kofsA = (c & 3) * KC;
        __syncthreads();

        {
            int row = t >> 2;
            int ks = (t & 3) * 8;
            int grow = block_row + row;
            uint4 v = make_uint4(0, 0, 0, 0);
            if (grow < n)
                v = *(const uint4*)(Asrc + (size_t)grow * CH + kofsA + ks);
            *(uint4*)&As[row][ks] = v;
        }
        {
            size_t go = (size_t)bnn * 256 + c * KC + bks;
            *(uint4*)&Bs[bnn][bks]     = *(const uint4*)(Wt + go);
            *(uint4*)&Bs[bnn][bks + 8] = *(const uint4*)(Wt + go + 8);
        }
        __syncthreads();

        #pragma unroll
        for (int kk = 0; kk < KC; kk += 16) {
            int kw = kk + (lane & 3) * 2;
            int rr = wm * 32 + (lane >> 2);
            uint32_t a_f[2][4], b_f[4][2];
            #pragma unroll
            for (int mi = 0; mi < 2; mi++) {
                int r = rr + mi * 16;
                a_f[mi][0] = *(uint32_t*)&As[r][kw];
                a_f[mi][1] = *(uint32_t*)&As[r + 8][kw];
                a_f[mi][2] = *(uint32_t*)&As[r][kw + 8];
                a_f[mi][3] = *(uint32_t*)&As[r + 8][kw + 8];
            }
            #pragma unroll
            for (int nj = 0; nj < 4; nj++) {
                int cn = wn * 32 + nj * 8 + (lane >> 2);
                b_f[nj][0] = *(uint32_t*)&Bs[cn][kw];
                b_f[nj][1] = *(uint32_t*)&Bs[cn][kw + 8];
            }
            #pragma unroll
            for (int mi = 0; mi < 2; mi++)
                #pragma unroll
                for (int nj = 0; nj < 4; nj++)
                    mma_f16(acc[mi][nj], a_f[mi], b_f[nj]);
        }
    }

    // ================= epilogue 1 =================
    if (MODE == 1) {
        #pragma unroll
        for (int mi = 0; mi < 2; mi++)
            #pragma unroll
            for (int part = 0; part < 2; part++) {
                int grow = block_row + wm * 32 + mi * 16 + part * 8 + (lane >> 2);
                if (grow < n) {
                    #pragma unroll
                    for (int nj = 0; nj < 4; nj++) {
                        int gcol = wn * 32 + nj * 8 + (lane & 3) * 2;
                        float v0 = acc[mi][nj][part * 2 + 0] + s_bias[gcol];
                        float v1 = acc[mi][nj][part * 2 + 1] + s_bias[gcol + 1];
                        *(uint32_t*)(g_h1h + (size_t)grow * CH + gcol) =
                            h2pack(fmaxf(v0, 0.f), fmaxf(v1, 0.f));
                    }
                }
            }
        return;
    }

    // MODE 2: write relu(h2) into smem H2 (stays on-chip)
    __syncthreads();
    #pragma unroll
    for (int mi = 0; mi < 2; mi++)
        #pragma unroll
        for (int part = 0; part < 2; part++) {
            int row = wm * 32 + mi * 16 + part * 8 + (lane >> 2);
            #pragma unroll
            for (int nj = 0; nj < 4; nj++) {
                int gcol = wn * 32 + nj * 8 + (lane & 3) * 2;
                float v0 = acc[mi][nj][part * 2 + 0] + s_bias[gcol];
                float v1 = acc[mi][nj][part * 2 + 1] + s_bias[gcol + 1];
                *(uint32_t*)&H2[row][gcol] =
                    h2pack(fmaxf(v0, 0.f), fmaxf(v1, 0.f));
            }
        }

    // ================= GEMM 2 (decoder): H2 @ Wdt =================
    float acc2[2][4][4];
    #pragma unroll
    for (int mi = 0; mi < 2; mi++)
        #pragma unroll
        for (int nj = 0; nj < 4; nj++)
            #pragma unroll
            for (int q = 0; q < 4; q++) acc2[mi][nj][q] = 0.f;

    #pragma unroll 1
    for (int c = 0; c < 4; c++) {
        __syncthreads();
        {
            size_t go = (size_t)bnn * 128 + c * KC + bks;
            *(uint4*)&Bs[bnn][bks]     = *(const uint4*)(g_Wdt + go);
            *(uint4*)&Bs[bnn][bks + 8] = *(const uint4*)(g_Wdt + go + 8);
        }
        __syncthreads();

        #pragma unroll
        for (int kk = 0; kk < KC; kk += 16) {
            int kwB = kk + (lane & 3) * 2;
            int kwA = c * KC + kwB;
            int rr = wm * 32 + (lane >> 2);
            uint32_t a_f[2][4], b_f[4][2];
            #pragma unroll
            for (int mi = 0; mi < 2; mi++) {
                int r = rr + mi * 16;
                a_f[mi][0] = *(uint32_t*)&H2[r][kwA];
                a_f[mi][1] = *(uint32_t*)&H2[r + 8][kwA];
                a_f[mi][2] = *(uint32_t*)&H2[r][kwA + 8];
                a_f[mi][3] = *(uint32_t*)&H2[r + 8][kwA + 8];
            }
            #pragma unroll
            for (int nj = 0; nj < 4; nj++) {
                int cn = wn * 32 + nj * 8 + (lane >> 2);
                b_f[nj][0] = *(uint32_t*)&Bs[cn][kwB];
                b_f[nj][1] = *(uint32_t*)&Bs[cn][kwB + 8];
            }
            #pragma unroll
            for (int mi = 0; mi < 2; mi++)
                #pragma unroll
                for (int nj = 0; nj < 4; nj++)
                    mma_f16(acc2[mi][nj], a_f[mi], b_f[nj]);
        }
    }

    // ================= epilogue 2: bias + residual =================
    float alpha = *alpha_p;
    float one_m = 1.0f - alpha;
    #pragma unroll
    for (int mi = 0; mi < 2; mi++)
        #pragma unroll
        for (int part = 0; part < 2; part++) {
            int grow = block_row + wm * 32 + mi * 16 + part * 8 + (lane >> 2);
            if (grow < n) {
                #pragma unroll
                for (int nj = 0; nj < 4; nj++) {
                    int gcol = wn * 32 + nj * 8 + (lane & 3) * 2;
                    float v0 = acc2[mi][nj][part * 2 + 0] + s_bd[gcol];
                    float v1 = acc2[mi][nj][part * 2 + 1] + s_bd[gcol + 1];
                    size_t o = (size_t)grow * CH + gcol;
                    float2 xv = *(const float2*)(xres + o);
                    float2 ov;
                    ov.x = alpha * v0 + one_m * xv.x;
                    ov.y = alpha * v1 + one_m * xv.y;
                    *(float2*)(out_ext + o) = ov;
                }
            }
        }
}

// ---------------------------------------------------------------------------
extern "C" void kernel_launch(void* const* d_in, const int* in_sizes, int n_in,
                              void* d_out, int out_size) {
    const float* x     = (const float*)d_in[0];
    const void*  edge  = d_in[1];
    const float* W1_l  = (const float*)d_in[2];
    const float* b1    = (const float*)d_in[3];
    const float* W1_r  = (const float*)d_in[4];
    const float* W2_l  = (const float*)d_in[5];
    const float* b2    = (const float*)d_in[6];
    const float* W2_r  = (const float*)d_in[7];
    const float* Wd    = (const float*)d_in[8];
    const float* bd    = (const float*)d_in[9];
    const float* alpha = (const float*)d_in[10];
    float* out = (float*)d_out;

    int n = in_sizes[0] / CH;            // 50000
    int E = in_sizes[1] / 2;             // 640000
    if (E > EMAX) E = EMAX;

    int pb = (n * CH / 8 + 255) / 256;   // 3125 (covers all prep work)
    int eb = (E / 4 + 255) / 256;        // 625
    int ab = (n * 32 + 255) / 256;
    int gb = (n + BM - 1) / BM;          // 782

    // prep (x->fp16 + clear cnt + weights->fp16T + detect), then CSR build
    prep_kernel<<<pb, 256>>>((const unsigned*)edge, x,
                             W1_l, W1_r, W2_l, W2_r, Wd, n);
    hist_kernel<<<eb, 256>>>(edge, E, n);
    scan_kernel<<<1, 1024>>>(n, E);
    fill_kernel<<<eb, 256>>>(edge, E, n);

    // Layer 1
    aggregate_kernel<0><<<ab, 256>>>(n);
    gemm_kernel<1><<<gb, 256>>>(b1, nullptr, nullptr, nullptr, nullptr, n);
    // Layer 2 + decoder + residual (fused)
    aggregate_kernel<1><<<ab, 256>>>(n);
    gemm_kernel<2><<<gb, 256>>>(b2, bd, x, alpha, out, n);
}